// round 11
// baseline (speedup 1.0000x reference)
#include <cuda_runtime.h>
#include <cstdint>
#include <cstddef>

#define T_STEPS 2048
#define BATCH   512
#define HID     33
#define G4      132
#define ODIM    18
#define H1DIM   72
#define CS      128
#define NCHUNK  16
#define NWAVE   20   // 16 chunks + 4 pipeline stages

// Static device scratch (allocation-free).
// xg buffers: [T][B][unit*4+gate] gate preactivations, biases absorbed.
__device__ float g_xg0[(size_t)T_STEPS * BATCH * G4];
__device__ float g_xg1[(size_t)T_STEPS * BATCH * G4];
__device__ float g_xg2[(size_t)T_STEPS * BATCH * G4];
__device__ float g_y0[(size_t)T_STEPS * BATCH * HID];
__device__ float g_y1[(size_t)T_STEPS * BATCH * HID];
__device__ float g_h[3][BATCH][HID];
__device__ float g_c[3][BATCH][HID];

typedef unsigned long long u64;

__device__ __forceinline__ void fma2(u64 &acc, u64 a, u64 b) {
    asm("fma.rn.f32x2 %0, %1, %2, %0;" : "+l"(acc) : "l"(a), "l"(b));
}
__device__ __forceinline__ u64 pack2(float lo, float hi) {
    u64 r; asm("mov.b64 %0, {%1,%2};" : "=l"(r) : "f"(lo), "f"(hi)); return r;
}
__device__ __forceinline__ float2 unpack2(u64 v) {
    float2 r; asm("mov.b64 {%0,%1}, %2;" : "=f"(r.x), "=f"(r.y) : "l"(v)); return r;
}
__device__ __forceinline__ float sigm_(float x) {
    return __fdividef(1.f, 1.f + __expf(-x));
}
__device__ __forceinline__ float tanh_(float x) {
    float e = __expf(2.f * x);
    return 1.f - __fdividef(2.f, e + 1.f);
}

// ---------------------------------------------------------------------------
// xg0: xg0[t][b][u*4+gb] = Wih0[gb*33+u]·x_t(b) + b_ih + b_hh  (IN=11)
// x layout [B,T,11]. One block = 1 t × 16 b. (R8-proven structure.)
// ---------------------------------------------------------------------------
__global__ __launch_bounds__(G4)
void xg0_kernel(const float* __restrict__ xin, const float* __restrict__ Wih,
                const float* __restrict__ bih, const float* __restrict__ bhh)
{
    const int t  = blockIdx.y;
    const int b0 = blockIdx.x * 16;
    const int j  = threadIdx.x;
    const int u  = j % 33, gb = j / 33;

    __shared__ __align__(16) float x_sh[16][12];
    for (int i = j; i < 16 * 12; i += G4) (&x_sh[0][0])[i] = 0.f;
    __syncthreads();
    for (int i = j; i < 16 * 11; i += G4)
        x_sh[i / 11][i % 11] = xin[((size_t)(b0 + i / 11) * T_STEPS + t) * 11 + (i % 11)];
    __syncthreads();

    u64 w2[6];
#pragma unroll
    for (int p = 0; p < 6; p++) {
        int m = 2 * p;
        float lo = (m     < 11) ? Wih[j * 11 + m]     : 0.f;
        float hi = (m + 1 < 11) ? Wih[j * 11 + m + 1] : 0.f;
        w2[p] = pack2(lo, hi);
    }
    const float bias = bih[j] + bhh[j];

    float* outp = g_xg0 + ((size_t)t * BATCH + b0) * G4 + u * 4 + gb;
#pragma unroll 4
    for (int g = 0; g < 16; g++) {
        u64 a0 = 0ull, a1 = 0ull;
        const ulonglong2* xv = (const ulonglong2*)x_sh[g];
#pragma unroll
        for (int q = 0; q < 3; q++) {
            ulonglong2 d = xv[q];
            fma2(a0, w2[2 * q],     d.x);
            fma2(a1, w2[2 * q + 1], d.y);
        }
        float2 u0 = unpack2(a0), u1 = unpack2(a1);
        outp[(size_t)g * G4] = (u0.x + u0.y) + (u1.x + u1.y) + bias;
    }
}

// ---------------------------------------------------------------------------
// xg role (IN=33): one CTA = 4 t × 16 b of one chunk; reads y[T,B,33].
// ---------------------------------------------------------------------------
__device__ __forceinline__ void xg_chunk(
    int chunk, const float* __restrict__ yb,
    const float* __restrict__ Wih,
    const float* __restrict__ bih, const float* __restrict__ bhh,
    float* __restrict__ xgbuf, float* sh)
{
    const int j  = threadIdx.x;
    const int bg = blockIdx.x & 31, tg = blockIdx.x >> 5;    // 32 x 32
    const int t0 = chunk * CS + tg * 4, b0 = bg * 16;
    float (*xs)[16][36] = (float(*)[16][36])sh;

    for (int i = j; i < 4 * 16 * 36; i += G4) sh[i] = 0.f;
    __syncthreads();
    for (int i = j; i < 4 * 16 * 33; i += G4) {
        int tt = i / 528, rem = i % 528, bb = rem / 33, kk = rem % 33;
        xs[tt][bb][kk] = yb[((size_t)(t0 + tt) * BATCH + b0 + bb) * HID + kk];
    }
    __syncthreads();

    u64 w2[18];
#pragma unroll
    for (int p = 0; p < 18; p++) {
        int m = 2 * p;
        float lo = (m     < HID) ? Wih[j * HID + m]     : 0.f;
        float hi = (m + 1 < HID) ? Wih[j * HID + m + 1] : 0.f;
        w2[p] = pack2(lo, hi);
    }
    const float bias = bih[j] + bhh[j];
    const int u = j % 33, gb = j / 33;

#pragma unroll
    for (int tt = 0; tt < 4; tt++) {
        float* outp = xgbuf + ((size_t)(t0 + tt) * BATCH + b0) * G4 + u * 4 + gb;
#pragma unroll 4
        for (int bb = 0; bb < 16; bb++) {
            u64 a0 = 0ull, a1 = 0ull;
            const ulonglong2* xv = (const ulonglong2*)xs[tt][bb];
#pragma unroll
            for (int q = 0; q < 9; q++) {
                ulonglong2 d = xv[q];
                fma2(a0, w2[2 * q],     d.x);
                fma2(a1, w2[2 * q + 1], d.y);
            }
            float2 u0 = unpack2(a0), u1 = unpack2(a1);
            outp[(size_t)bb * G4] = (u0.x + u0.y) + (u1.x + u1.y) + bias;
        }
    }
}

// ---------------------------------------------------------------------------
// Recurrence role: unit-per-thread. CTA = 4 batch elems x 33 threads.
// Thread (e,u): all 4 gates of unit u via 4 interleaved 18-pair f32x2 chains
// over shared h; xg streamed as one float4/step (depth-4 ring, chunk-clamped).
// Thread-local cell update -> ONE __syncthreads per step, zero shuffles.
// ---------------------------------------------------------------------------
template<bool YW>
__device__ __forceinline__ void lstm_step(
    int s, int t0, int e, int u, int b, float4& rr,
    const u64 (&w)[4][18], float (*h_sh)[2][36],
    float& c, float& hval,
    const float4* __restrict__ xp, size_t xstr,
    float* __restrict__ yout, float* __restrict__ hid)
{
    const int t = t0 + s;
    const int pc = s & 1, pn = pc ^ 1;

    u64 aI = 0ull, aF = 0ull, aG = 0ull, aO = 0ull;
    const ulonglong2* hv = (const ulonglong2*)h_sh[e][pc];
#pragma unroll
    for (int q = 0; q < 9; q++) {
        ulonglong2 d = hv[q];
        fma2(aI, w[0][2 * q], d.x); fma2(aI, w[0][2 * q + 1], d.y);
        fma2(aF, w[1][2 * q], d.x); fma2(aF, w[1][2 * q + 1], d.y);
        fma2(aG, w[2][2 * q], d.x); fma2(aG, w[2][2 * q + 1], d.y);
        fma2(aO, w[3][2 * q], d.x); fma2(aO, w[3][2 * q + 1], d.y);
    }
    float2 eI = unpack2(aI), eF = unpack2(aF), eG = unpack2(aG), eO = unpack2(aO);
    float gi = sigm_(eI.x + eI.y + rr.x);
    float gf = sigm_(eF.x + eF.y + rr.y);
    float gg = tanh_(eG.x + eG.y + rr.z);
    float go = sigm_(eO.x + eO.y + rr.w);
    c    = gf * c + gi * gg;
    hval = go * tanh_(c);
    h_sh[e][pn][u] = hval;
    if (YW) yout[((size_t)t * BATCH + b) * HID + u] = hval;
    if (t == T_STEPS - 1) hid[b * HID + u] = hval;
    if (s + 4 < CS) rr = __ldg(xp + (size_t)(s + 4) * xstr);   // chunk-clamped
    __syncthreads();
}

template<bool YW>
__device__ __forceinline__ void rec_chunk(
    int chunk, int layer,
    const float* __restrict__ xgbuf,
    const float* __restrict__ Whh,
    float* __restrict__ yout,
    float* __restrict__ hid,
    float* sh)
{
    const int tid = threadIdx.x;
    const int e   = tid / 33, u = tid % 33;
    const int b   = blockIdx.x * 4 + e;
    const int t0  = chunk * CS;
    float (*h_sh)[2][36] = (float(*)[2][36])sh;

    u64 w[4][18];
#pragma unroll
    for (int gb = 0; gb < 4; gb++) {
        const float* wr = Whh + (gb * HID + u) * HID;
#pragma unroll
        for (int p = 0; p < 18; p++) {
            int m = 2 * p;
            float lo = (m     < HID) ? wr[m]     : 0.f;
            float hi = (m + 1 < HID) ? wr[m + 1] : 0.f;
            w[gb][p] = pack2(lo, hi);
        }
    }

    for (int i = tid; i < 4 * 2 * 36; i += G4) sh[i] = 0.f;
    __syncthreads();
    float c = 0.f;
    if (chunk > 0) {
        c = g_c[layer][b][u];
        h_sh[e][0][u] = g_h[layer][b][u];
    }
    __syncthreads();

    const float4* xp = (const float4*)xgbuf + ((size_t)t0 * BATCH + b) * 33 + u;
    const size_t xstr = (size_t)BATCH * 33;   // float4 stride per t
    float4 r0 = __ldg(xp);
    float4 r1 = __ldg(xp + xstr);
    float4 r2 = __ldg(xp + 2 * xstr);
    float4 r3 = __ldg(xp + 3 * xstr);

    float hval = 0.f;
    for (int s = 0; s < CS; s += 4) {
        lstm_step<YW>(s + 0, t0, e, u, b, r0, w, h_sh, c, hval, xp, xstr, yout, hid);
        lstm_step<YW>(s + 1, t0, e, u, b, r1, w, h_sh, c, hval, xp, xstr, yout, hid);
        lstm_step<YW>(s + 2, t0, e, u, b, r2, w, h_sh, c, hval, xp, xstr, yout, hid);
        lstm_step<YW>(s + 3, t0, e, u, b, r3, w, h_sh, c, hval, xp, xstr, yout, hid);
    }

    g_h[layer][b][u] = hval;
    g_c[layer][b][u] = c;
}

// ---------------------------------------------------------------------------
// Pipeline wave. Stages: rec0=0, xg1=1, rec1=2, xg2=3, rec2=4.
// Rec roles use blockIdx.x < 128 (4 elems/CTA); xg roles use 1024 CTAs.
// All producer->consumer deps are cross-launch (stream order).
// ---------------------------------------------------------------------------
__global__ __launch_bounds__(G4, 2)
void wave_kernel(int w,
                 const float* __restrict__ Wih1, const float* __restrict__ Whh0,
                 const float* __restrict__ bih1, const float* __restrict__ bhh1,
                 const float* __restrict__ Whh1,
                 const float* __restrict__ Wih2, const float* __restrict__ bih2,
                 const float* __restrict__ bhh2, const float* __restrict__ Whh2,
                 float* __restrict__ hid)
{
    __shared__ __align__(16) float sh[4 * 16 * 36];   // 9216 B (max role need)
    const int role = blockIdx.y;

    if (role == 0) {
        int chunk = w;
        if ((unsigned)chunk >= NCHUNK || blockIdx.x >= 128) return;
        rec_chunk<true >(chunk, 0, g_xg0, Whh0, g_y0, hid, sh);
    } else if (role == 1) {
        int chunk = w - 1;
        if ((unsigned)chunk >= NCHUNK) return;
        xg_chunk(chunk, g_y0, Wih1, bih1, bhh1, g_xg1, sh);
    } else if (role == 2) {
        int chunk = w - 2;
        if ((unsigned)chunk >= NCHUNK || blockIdx.x >= 128) return;
        rec_chunk<true >(chunk, 1, g_xg1, Whh1, g_y1, hid + BATCH * HID, sh);
    } else if (role == 3) {
        int chunk = w - 3;
        if ((unsigned)chunk >= NCHUNK) return;
        xg_chunk(chunk, g_y1, Wih2, bih2, bhh2, g_xg2, sh);
    } else {
        int chunk = w - 4;
        if ((unsigned)chunk >= NCHUNK || blockIdx.x >= 128) return;
        rec_chunk<false>(chunk, 2, g_xg2, Whh2, nullptr, hid + 2 * BATCH * HID, sh);
    }
}

// ---------------------------------------------------------------------------
// MLP head: out = GELU(hid@W1^T + b1) @ W2^T + b2
// ---------------------------------------------------------------------------
__global__ __launch_bounds__(H1DIM)
void head_kernel(const float* __restrict__ hid,
                 const float* __restrict__ W1, const float* __restrict__ b1,
                 const float* __restrict__ W2, const float* __restrict__ b2,
                 float* __restrict__ out)
{
    const int rr = blockIdx.x;
    const int u  = threadIdx.x;
    __shared__ float hrow[HID];
    __shared__ float h1[H1DIM];

    if (u < HID) hrow[u] = hid[rr * HID + u];
    __syncthreads();

    float s = b1[u];
#pragma unroll
    for (int m = 0; m < HID; m++) s += W1[u * HID + m] * hrow[m];
    h1[u] = 0.5f * s * (1.f + erff(s * 0.70710678118654752f));  // exact GELU
    __syncthreads();

    if (u < ODIM) {
        float s2 = b2[u];
#pragma unroll
        for (int m = 0; m < H1DIM; m++) s2 += W2[u * H1DIM + m] * h1[m];
        out[rr * ODIM + u] = s2;
    }
}

extern "C" void kernel_launch(void* const* d_in, const int* in_sizes, int n_in,
                              void* d_out, int out_size)
{
    const float* x    = (const float*)d_in[0];
    const float* Wih0 = (const float*)d_in[1];
    const float* Whh0 = (const float*)d_in[2];
    const float* bih0 = (const float*)d_in[3];
    const float* bhh0 = (const float*)d_in[4];
    const float* Wih1 = (const float*)d_in[5];
    const float* Whh1 = (const float*)d_in[6];
    const float* bih1 = (const float*)d_in[7];
    const float* bhh1 = (const float*)d_in[8];
    const float* Wih2 = (const float*)d_in[9];
    const float* Whh2 = (const float*)d_in[10];
    const float* bih2 = (const float*)d_in[11];
    const float* bhh2 = (const float*)d_in[12];
    const float* W1   = (const float*)d_in[13];
    const float* b1   = (const float*)d_in[14];
    const float* W2   = (const float*)d_in[15];
    const float* b2   = (const float*)d_in[16];

    float* out = (float*)d_out;                      // [3, 512, 18]
    float* hid = out + 3 * BATCH * ODIM;             // [3, 512, 33]

    // xg0 depends only on the input: one upfront throughput pass.
    xg0_kernel<<<dim3(BATCH / 16, T_STEPS), G4>>>(x, Wih0, bih0, bhh0);

    dim3 wgrid(1024, 5);
    for (int w = 0; w < NWAVE; ++w) {
        wave_kernel<<<wgrid, G4>>>(w,
                                   Wih1, Whh0, bih1, bhh1, Whh1,
                                   Wih2, bih2, bhh2, Whh2, hid);
    }
    head_kernel<<<3 * BATCH, H1DIM>>>(hid, W1, b1, W2, b2, out);
}

// round 12
// speedup vs baseline: 1.2287x; 1.2287x over previous
#include <cuda_runtime.h>
#include <cstdint>
#include <cstddef>

#define T_STEPS 2048
#define BATCH   512
#define HID     33
#define G4      132
#define ODIM    18
#define H1DIM   72
#define CS      128
#define NCHUNK  16
#define NWAVE   20    // 16 chunks + 4 pipeline stages

// Static device scratch (allocation-free).
// xg layout per t,b: [unit*4+gate] so a rec lane reads one float4.
__device__ float g_xg0[(size_t)T_STEPS * BATCH * G4];
__device__ float g_xg1[(size_t)T_STEPS * BATCH * G4];
__device__ float g_xg2[(size_t)T_STEPS * BATCH * G4];
__device__ float g_y0[(size_t)T_STEPS * BATCH * HID];
__device__ float g_y1[(size_t)T_STEPS * BATCH * HID];
__device__ float g_h[3][BATCH][HID];
__device__ float g_c[3][BATCH][HID];

typedef unsigned long long u64;

__device__ __forceinline__ void fma2(u64 &acc, u64 a, u64 b) {
    asm("fma.rn.f32x2 %0, %1, %2, %0;" : "+l"(acc) : "l"(a), "l"(b));
}
__device__ __forceinline__ u64 pack2(float lo, float hi) {
    u64 r; asm("mov.b64 %0, {%1,%2};" : "=l"(r) : "f"(lo), "f"(hi)); return r;
}
__device__ __forceinline__ float2 unpack2(u64 v) {
    float2 r; asm("mov.b64 {%0,%1}, %2;" : "=f"(r.x), "=f"(r.y) : "l"(v)); return r;
}
__device__ __forceinline__ float sigm_(float x) {
    return __fdividef(1.f, 1.f + __expf(-x));
}
__device__ __forceinline__ float tanh_(float x) {
    float e = __expf(2.f * x);
    return 1.f - __fdividef(2.f, e + 1.f);
}

// ---------------------------------------------------------------------------
// xg0 upfront (IN=11, x layout [B,T,11]): proven R8/R11 structure.
// ---------------------------------------------------------------------------
__global__ __launch_bounds__(G4)
void xg0_kernel(const float* __restrict__ xin, const float* __restrict__ Wih,
                const float* __restrict__ bih, const float* __restrict__ bhh)
{
    const int t  = blockIdx.y;
    const int b0 = blockIdx.x * 16;
    const int j  = threadIdx.x;
    const int u  = j % 33, gb = j / 33;

    __shared__ __align__(16) float x_sh[16][12];
    for (int i = j; i < 16 * 12; i += G4) (&x_sh[0][0])[i] = 0.f;
    __syncthreads();
    for (int i = j; i < 16 * 11; i += G4)
        x_sh[i / 11][i % 11] = xin[((size_t)(b0 + i / 11) * T_STEPS + t) * 11 + (i % 11)];
    __syncthreads();

    u64 w2[6];
#pragma unroll
    for (int p = 0; p < 6; p++) {
        int m = 2 * p;
        float lo = (m     < 11) ? Wih[j * 11 + m]     : 0.f;
        float hi = (m + 1 < 11) ? Wih[j * 11 + m + 1] : 0.f;
        w2[p] = pack2(lo, hi);
    }
    const float bias = bih[j] + bhh[j];

    float* outp = g_xg0 + ((size_t)t * BATCH + b0) * G4 + u * 4 + gb;
#pragma unroll 4
    for (int g = 0; g < 16; g++) {
        u64 a0 = 0ull, a1 = 0ull;
        const ulonglong2* xv = (const ulonglong2*)x_sh[g];
#pragma unroll
        for (int q = 0; q < 3; q++) {
            ulonglong2 d = xv[q];
            fma2(a0, w2[2 * q],     d.x);
            fma2(a1, w2[2 * q + 1], d.y);
        }
        float2 u0 = unpack2(a0), u1 = unpack2(a1);
        outp[(size_t)g * G4] = (u0.x + u0.y) + (u1.x + u1.y) + bias;
    }
}

// ---------------------------------------------------------------------------
// xg role (IN=33): one CTA = 4 t x 16 b of one chunk; reads y[T,B,33].
// Pure-throughput filler work co-resident with the latency-bound rec warps.
// ---------------------------------------------------------------------------
__device__ __forceinline__ void xg_chunk(
    int chunk, const float* __restrict__ yb,
    const float* __restrict__ Wih,
    const float* __restrict__ bih, const float* __restrict__ bhh,
    float* __restrict__ xgbuf, float* sh)
{
    const int j  = threadIdx.x;
    const int bg = blockIdx.x & 31, tg = blockIdx.x >> 5;    // 32 x 32
    const int t0 = chunk * CS + tg * 4, b0 = bg * 16;
    float (*xs)[16][36] = (float(*)[16][36])sh;

    for (int i = j; i < 4 * 16 * 36; i += G4) sh[i] = 0.f;
    __syncthreads();
    for (int i = j; i < 4 * 16 * 33; i += G4) {
        int tt = i / 528, rem = i % 528, bb = rem / 33, kk = rem % 33;
        xs[tt][bb][kk] = yb[((size_t)(t0 + tt) * BATCH + b0 + bb) * HID + kk];
    }
    __syncthreads();

    u64 w2[18];
#pragma unroll
    for (int p = 0; p < 18; p++) {
        int m = 2 * p;
        float lo = (m     < HID) ? Wih[j * HID + m]     : 0.f;
        float hi = (m + 1 < HID) ? Wih[j * HID + m + 1] : 0.f;
        w2[p] = pack2(lo, hi);
    }
    const float bias = bih[j] + bhh[j];
    const int u = j % 33, gb = j / 33;

#pragma unroll
    for (int tt = 0; tt < 4; tt++) {
        float* outp = xgbuf + ((size_t)(t0 + tt) * BATCH + b0) * G4 + u * 4 + gb;
#pragma unroll 4
        for (int bb = 0; bb < 16; bb++) {
            u64 a0 = 0ull, a1 = 0ull;
            const ulonglong2* xv = (const ulonglong2*)xs[tt][bb];
#pragma unroll
            for (int q = 0; q < 9; q++) {
                ulonglong2 d = xv[q];
                fma2(a0, w2[2 * q],     d.x);
                fma2(a1, w2[2 * q + 1], d.y);
            }
            float2 u0 = unpack2(a0), u1 = unpack2(a1);
            outp[(size_t)bb * G4] = (u0.x + u0.y) + (u1.x + u1.y) + bias;
        }
    }
}

// ---------------------------------------------------------------------------
// Rec role: R8's proven warp-local recurrence, chunked. ONE WARP per element,
// NO barriers in the t-loop. Lane l owns unit l (4 register rows); unit 32 via
// a 5th shared-weight chain on lanes 0..3 + shuffle broadcast. xg via float4
// depth-4 register ring (chunk-clamped). h double-buffered per-warp in shared.
// Uses threads 0..127 of the 132-thread block (rest exit immediately).
// ---------------------------------------------------------------------------
template<bool YW>
__device__ __forceinline__ void rec_chunk(
    int chunk, int layer,
    const float* __restrict__ xgbuf, const float* __restrict__ Whh,
    float* __restrict__ yout, float* __restrict__ hid, float* shbase)
{
    const int tid  = threadIdx.x;      // < 128 guaranteed by caller
    const int e    = tid >> 5;
    const int lane = tid & 31;
    const int b    = blockIdx.x * 4 + e;
    const int t0   = chunk * CS;

    float (*h_sh)[2][36] = (float(*)[2][36])shbase;                  // 1152 B
    u64   (*w5_sh)[18]   = (u64(*)[18])(shbase + 4 * 2 * 36);        // 576 B

    // setup (exited threads don't count toward barriers)
    for (int i = tid; i < 4 * 2 * 36; i += 128) (&h_sh[0][0][0])[i] = 0.f;
    if (tid < 68) {
        int rk = tid / 17, p = tid % 17;
        int row = rk * 33 + 32;
        float lo = Whh[row * HID + 2 * p];
        float hi = (2 * p + 1 < HID) ? Whh[row * HID + 2 * p + 1] : 0.f;
        w5_sh[rk][p] = pack2(lo, hi);
    }
    if (tid >= 68 && tid < 72) w5_sh[tid - 68][17] = 0ull;
    __syncthreads();

    // own-unit weights, f32x2-packed over k (17 pairs; slot 33 zeroed)
    u64 w0[17], w1[17], w2[17], w3[17];
#pragma unroll
    for (int p = 0; p < 17; p++) {
        int m = 2 * p;
        float hm = (m + 1 < HID) ? 1.f : 0.f;
        int m1 = (m + 1 < HID) ? m + 1 : 0;
        w0[p] = pack2(Whh[(0 * 33 + lane) * HID + m], hm * Whh[(0 * 33 + lane) * HID + m1]);
        w1[p] = pack2(Whh[(1 * 33 + lane) * HID + m], hm * Whh[(1 * 33 + lane) * HID + m1]);
        w2[p] = pack2(Whh[(2 * 33 + lane) * HID + m], hm * Whh[(2 * 33 + lane) * HID + m1]);
        w3[p] = pack2(Whh[(3 * 33 + lane) * HID + m], hm * Whh[(3 * 33 + lane) * HID + m1]);
    }

    const int l4 = (lane < 3) ? lane : 3;
    const ulonglong2* w5v = (const ulonglong2*)w5_sh[l4];
    const u64 w5t = w5_sh[l4][16];
    // lane 2 computes g_32: tanh(x) = 2*sigm(2x) - 1
    const float S5 = (lane == 2) ? 2.f : 1.f;
    const float A5 = (lane == 2) ? 2.f : 1.f;
    const float B5 = (lane == 2) ? -1.f : 0.f;

    // seed chunk state
    float c = 0.f, c5 = 0.f;
    if (chunk > 0) {
        c  = g_c[layer][b][lane];
        c5 = g_c[layer][b][32];          // broadcast load (uniform)
        h_sh[e][0][lane] = g_h[layer][b][lane];
        if (lane == 0) h_sh[e][0][32] = g_h[layer][b][32];
    }
    __syncwarp();

    // xg ring: one float4 (own unit's 4 gates) + one float (unit-32 gate l4)
    const float*  xgb  = xgbuf + ((size_t)t0 * BATCH + b) * G4;
    const float4* xg4p = (const float4*)xgb + lane;
    const float*  xg5p = xgb + 128 + l4;
    const size_t  s4 = (size_t)BATCH * 33;     // float4 per-t stride
    const size_t  s1 = (size_t)BATCH * G4;     // float  per-t stride
    float4 r0 = __ldg(xg4p), r1 = __ldg(xg4p + s4),
           r2 = __ldg(xg4p + 2 * s4), r3 = __ldg(xg4p + 3 * s4);
    float  q0 = __ldg(xg5p), q1 = __ldg(xg5p + s1),
           q2 = __ldg(xg5p + 2 * s1), q3 = __ldg(xg5p + 3 * s1);

    float hval = 0.f, h5 = 0.f;

    for (int s = 0; s < CS; ++s) {
        const int t  = t0 + s;
        const int pc = s & 1, pn = pc ^ 1;

        float4 xg4 = r0; float xg5 = q0;
        r0 = r1; r1 = r2; r2 = r3;
        q0 = q1; q1 = q2; q2 = q3;
        if (s + 4 < CS) {                 // chunk-clamped prefetch
            r3 = __ldg(xg4p + (size_t)(s + 4) * s4);
            q3 = __ldg(xg5p + (size_t)(s + 4) * s1);
        }

        u64 a0 = 0ull, a1 = 0ull, a2 = 0ull, a3 = 0ull, a4 = 0ull;
        const ulonglong2* hv = (const ulonglong2*)h_sh[e][pc];
#pragma unroll
        for (int q = 0; q < 8; q++) {
            ulonglong2 v = hv[q];
            fma2(a0, w0[2 * q], v.x); fma2(a0, w0[2 * q + 1], v.y);
            fma2(a1, w1[2 * q], v.x); fma2(a1, w1[2 * q + 1], v.y);
            fma2(a2, w2[2 * q], v.x); fma2(a2, w2[2 * q + 1], v.y);
            fma2(a3, w3[2 * q], v.x); fma2(a3, w3[2 * q + 1], v.y);
            ulonglong2 wq = w5v[q];
            fma2(a4, wq.x, v.x);      fma2(a4, wq.y, v.y);
        }
        u64 vt = ((const u64*)h_sh[e][pc])[16];   // (h32, 0)
        fma2(a0, w0[16], vt); fma2(a1, w1[16], vt);
        fma2(a2, w2[16], vt); fma2(a3, w3[16], vt);
        fma2(a4, w5t, vt);

        float2 f0 = unpack2(a0), f1 = unpack2(a1), f2 = unpack2(a2),
               f3 = unpack2(a3), f4 = unpack2(a4);
        float gi = sigm_(f0.x + f0.y + xg4.x);
        float gf = sigm_(f1.x + f1.y + xg4.y);
        float gg = tanh_(f2.x + f2.y + xg4.z);
        float go = sigm_(f3.x + f3.y + xg4.w);
        float g5 = A5 * sigm_(S5 * (f4.x + f4.y + xg5)) + B5;

        float i32 = __shfl_sync(0xFFFFFFFFu, g5, 0);
        float f32 = __shfl_sync(0xFFFFFFFFu, g5, 1);
        float g32 = __shfl_sync(0xFFFFFFFFu, g5, 2);
        float o32 = __shfl_sync(0xFFFFFFFFu, g5, 3);

        c    = gf * c + gi * gg;
        c5   = f32 * c5 + i32 * g32;
        hval = go  * tanh_(c);
        h5   = o32 * tanh_(c5);

        h_sh[e][pn][lane] = hval;
        if (lane == 0) h_sh[e][pn][32] = h5;

        if (YW) {
            float* yp = yout + ((size_t)t * BATCH + b) * HID;
            yp[lane] = hval;
            if (lane == 0) yp[32] = h5;
        }
        if (t == T_STEPS - 1) {
            hid[b * HID + lane] = hval;
            if (lane == 0) hid[b * HID + 32] = h5;
        }
        __syncwarp();
    }

    // persist chunk state
    g_h[layer][b][lane] = hval;
    g_c[layer][b][lane] = c;
    if (lane == 0) { g_h[layer][b][32] = h5; g_c[layer][b][32] = c5; }
}

// ---------------------------------------------------------------------------
// Pipeline wave. Roles: rec0=0, xg1=1, rec1=2, xg2=3, rec2=4.
// Rec roles: blockIdx.x < 128 (4 elems/CTA, warp-local, barrier-free).
// xg roles: 1024 CTAs of throughput work (fills rec latency gaps).
// Producer->consumer deps are cross-launch (stream order).
// ---------------------------------------------------------------------------
__global__ __launch_bounds__(G4, 2)
void wave_kernel(int w,
                 const float* __restrict__ Wih1, const float* __restrict__ Whh0,
                 const float* __restrict__ bih1, const float* __restrict__ bhh1,
                 const float* __restrict__ Whh1,
                 const float* __restrict__ Wih2, const float* __restrict__ bih2,
                 const float* __restrict__ bhh2, const float* __restrict__ Whh2,
                 float* __restrict__ hid)
{
    __shared__ __align__(16) float sh[4 * 16 * 36];   // 9216 B (xg role max)
    const int role = blockIdx.y;

    if (role == 1) {
        int chunk = w - 1;
        if ((unsigned)chunk >= NCHUNK) return;
        xg_chunk(chunk, g_y0, Wih1, bih1, bhh1, g_xg1, sh);
        return;
    }
    if (role == 3) {
        int chunk = w - 3;
        if ((unsigned)chunk >= NCHUNK) return;
        xg_chunk(chunk, g_y1, Wih2, bih2, bhh2, g_xg2, sh);
        return;
    }
    // rec roles
    if (blockIdx.x >= 128 || threadIdx.x >= 128) return;
    if (role == 0) {
        int chunk = w;
        if ((unsigned)chunk >= NCHUNK) return;
        rec_chunk<true >(chunk, 0, g_xg0, Whh0, g_y0, hid, sh);
    } else if (role == 2) {
        int chunk = w - 2;
        if ((unsigned)chunk >= NCHUNK) return;
        rec_chunk<true >(chunk, 1, g_xg1, Whh1, g_y1, hid + BATCH * HID, sh);
    } else {
        int chunk = w - 4;
        if ((unsigned)chunk >= NCHUNK) return;
        rec_chunk<false>(chunk, 2, g_xg2, Whh2, nullptr, hid + 2 * BATCH * HID, sh);
    }
}

// ---------------------------------------------------------------------------
// MLP head: out = GELU(hid@W1^T + b1) @ W2^T + b2
// ---------------------------------------------------------------------------
__global__ __launch_bounds__(H1DIM)
void head_kernel(const float* __restrict__ hid,
                 const float* __restrict__ W1, const float* __restrict__ b1,
                 const float* __restrict__ W2, const float* __restrict__ b2,
                 float* __restrict__ out)
{
    const int rr = blockIdx.x;
    const int u  = threadIdx.x;
    __shared__ float hrow[HID];
    __shared__ float h1[H1DIM];

    if (u < HID) hrow[u] = hid[rr * HID + u];
    __syncthreads();

    float s = b1[u];
#pragma unroll
    for (int m = 0; m < HID; m++) s += W1[u * HID + m] * hrow[m];
    h1[u] = 0.5f * s * (1.f + erff(s * 0.70710678118654752f));  // exact GELU
    __syncthreads();

    if (u < ODIM) {
        float s2 = b2[u];
#pragma unroll
        for (int m = 0; m < H1DIM; m++) s2 += W2[u * H1DIM + m] * h1[m];
        out[rr * ODIM + u] = s2;
    }
}

extern "C" void kernel_launch(void* const* d_in, const int* in_sizes, int n_in,
                              void* d_out, int out_size)
{
    const float* x    = (const float*)d_in[0];
    const float* Wih0 = (const float*)d_in[1];
    const float* Whh0 = (const float*)d_in[2];
    const float* bih0 = (const float*)d_in[3];
    const float* bhh0 = (const float*)d_in[4];
    const float* Wih1 = (const float*)d_in[5];
    const float* Whh1 = (const float*)d_in[6];
    const float* bih1 = (const float*)d_in[7];
    const float* bhh1 = (const float*)d_in[8];
    const float* Wih2 = (const float*)d_in[9];
    const float* Whh2 = (const float*)d_in[10];
    const float* bih2 = (const float*)d_in[11];
    const float* bhh2 = (const float*)d_in[12];
    const float* W1   = (const float*)d_in[13];
    const float* b1   = (const float*)d_in[14];
    const float* W2   = (const float*)d_in[15];
    const float* b2   = (const float*)d_in[16];

    float* out = (float*)d_out;                      // [3, 512, 18]
    float* hid = out + 3 * BATCH * ODIM;             // [3, 512, 33]

    // xg0 depends only on the input: one upfront throughput pass.
    xg0_kernel<<<dim3(BATCH / 16, T_STEPS), G4>>>(x, Wih0, bih0, bhh0);

    dim3 wgrid(1024, 5);
    for (int w = 0; w < NWAVE; ++w) {
        wave_kernel<<<wgrid, G4>>>(w,
                                   Wih1, Whh0, bih1, bhh1, Whh1,
                                   Wih2, bih2, bhh2, Whh2, hid);
    }
    head_kernel<<<3 * BATCH, H1DIM>>>(hid, W1, b1, W2, b2, out);
}

// round 13
// speedup vs baseline: 1.8553x; 1.5100x over previous
#include <cuda_runtime.h>
#include <cstdint>
#include <cstddef>

#define T_STEPS 2048
#define BATCH   512
#define HID     33
#define G4      132
#define ODIM    18
#define H1DIM   72

// Per-layer outputs y[t][b][k] (t-major). Static device scratch (no allocs).
__device__ float g_y0[(size_t)T_STEPS * BATCH * HID];
__device__ float g_y1[(size_t)T_STEPS * BATCH * HID];

typedef unsigned long long u64;

__device__ __forceinline__ void fma2(u64 &acc, u64 a, u64 b) {
    asm("fma.rn.f32x2 %0, %1, %2, %0;" : "+l"(acc) : "l"(a), "l"(b));
}
__device__ __forceinline__ u64 pack2(float lo, float hi) {
    u64 r; asm("mov.b64 %0, {%1,%2};" : "=l"(r) : "f"(lo), "f"(hi)); return r;
}
__device__ __forceinline__ float2 unpack2(u64 v) {
    float2 r; asm("mov.b64 {%0,%1}, %2;" : "=f"(r.x), "=f"(r.y) : "l"(v)); return r;
}
__device__ __forceinline__ float sigm_(float x) {
    return __fdividef(1.f, 1.f + __expf(-x));
}
__device__ __forceinline__ float tanh_(float x) {
    float e = __expf(2.f * x);
    return 1.f - __fdividef(2.f, e + 1.f);
}

// ---------------------------------------------------------------------------
// One CTA = one batch element (R5 structure). Thread j = 4*u + g computes the
// FULL fused gate dot for gate g (0=i,1=f,2=g,3=o) of unit u, exactly as R5
// (two f32x2 chains over h and x read from shared). Difference vs R5: the 4
// gates of a unit are adjacent lanes of one warp, so the cell update is done
// with 2 shuffles in-warp and the step needs only ONE __syncthreads (h and x
// both double-buffered).
//
// IN:   input width (11 for layer 0, 33 otherwise)
// XBF:  x layout [B,T,IN] (layer 0) vs [T,B,HID] (y buffers)
// XSRC: -1 = xin param, 0 = g_y0, 1 = g_y1
// YDST: -1 = no per-step output, 0 = g_y0, 1 = g_y1
// ---------------------------------------------------------------------------
template<int IN, bool XBF, int XSRC, int YDST>
__global__ __launch_bounds__(G4)
void lstm_layer_kernel(const float* __restrict__ xin,
                       const float* __restrict__ Wih,
                       const float* __restrict__ Whh,
                       const float* __restrict__ bih,
                       const float* __restrict__ bhh,
                       float* __restrict__ hid)
{
    constexpr int INP = ((IN + 3) / 4) * 4;   // 12 / 36
    constexpr int NPI = INP / 2;
    const int b = blockIdx.x;
    const int j = threadIdx.x;
    const int u = j >> 2;          // unit 0..32
    const int g = j & 3;           // gate 0=i,1=f,2=g,3=o

    const float* xp = (XSRC == 0) ? g_y0 : (XSRC == 1) ? g_y1 : xin;
    float* yp = (YDST == 0) ? g_y0 : (YDST == 1) ? g_y1 : nullptr;

    __shared__ __align__(16) float h_sh[2][36];
    __shared__ __align__(16) float x_sh[2][36];

    // weight row r = g*HID + u (PyTorch gate order i,f,g,o)
    const int r = g * HID + u;

    u64 whh2[18];
#pragma unroll
    for (int p = 0; p < 18; p++) {
        int m = 2 * p;
        float lo = (m     < HID) ? Whh[r * HID + m]     : 0.f;
        float hi = (m + 1 < HID) ? Whh[r * HID + m + 1] : 0.f;
        whh2[p] = pack2(lo, hi);
    }
    u64 wih2[NPI];
#pragma unroll
    for (int p = 0; p < NPI; p++) {
        int m = 2 * p;
        float lo = (m     < IN) ? Wih[r * IN + m]     : 0.f;
        float hi = (m + 1 < IN) ? Wih[r * IN + m + 1] : 0.f;
        wih2[p] = pack2(lo, hi);
    }
    const float bias = bih[r] + bhh[r];

    // shuffle mask for (possibly partial) last warp (tid 128..131 -> 0xF)
    const int lanebase = j & ~31;
    const int nlanes   = (G4 - lanebase >= 32) ? 32 : (G4 - lanebase);
    const unsigned mask = (nlanes == 32) ? 0xFFFFFFFFu : ((1u << nlanes) - 1u);

    const bool ldr = (g == 3) && (u < IN);   // x loader threads

    auto xval = [&](int t, int i) -> float {
        if (XBF) return xp[((size_t)b * T_STEPS + t) * IN + i];
        else     return xp[((size_t)t * BATCH + b) * HID + i];
    };

    // ---- init shared state (both parities zero; pads stay zero) ----
    for (int i = j; i < 2 * 36; i += G4) { h_sh[0][i % 36] = 0.f; }
    if (j < 72) { (&h_sh[0][0])[j] = 0.f; (&x_sh[0][0])[j] = 0.f; }
    __syncthreads();
    if (ldr) x_sh[0][u] = xval(0, u);
    __syncthreads();

    float c  = 0.f;                            // cell state (lives in lane g==1)
    float xr = ldr ? xval(1, u) : 0.f;         // x(t+1) entering step t

    for (int t = 0; t < T_STEPS; ++t) {
        const int pc = t & 1, pn = pc ^ 1;

        // depth-2 x prefetch (long-scoreboard hidden across steps)
        float xr2 = 0.f;
        if (ldr && (t + 2) < T_STEPS) xr2 = xval(t + 2, u);

        // fused gate pre-activation: two independent f32x2 chains (as R5)
        u64 acch = 0ull, accx = 0ull;
        const ulonglong2* hv = (const ulonglong2*)h_sh[pc];
        const ulonglong2* xv = (const ulonglong2*)x_sh[pc];
#pragma unroll
        for (int q = 0; q < 9; q++) {
            ulonglong2 v = hv[q];                 // LDS.128 broadcast
            fma2(acch, whh2[2 * q],     v.x);
            fma2(acch, whh2[2 * q + 1], v.y);
        }
#pragma unroll
        for (int q = 0; q < INP / 4; q++) {
            ulonglong2 v = xv[q];
            fma2(accx, wih2[2 * q],     v.x);
            fma2(accx, wih2[2 * q + 1], v.y);
        }
        float2 ah = unpack2(acch), ax = unpack2(accx);
        float pre = (ah.x + ah.y) + (ax.x + ax.y) + bias;
        float v   = (g == 2) ? tanh_(pre) : sigm_(pre);

        // in-warp cell update within the 4-lane unit group:
        //   t1 = partner across xor 2: lane0<-g, lane1<-o, lane2<-i, lane3<-f
        float t1 = __shfl_xor_sync(mask, v, 2);
        float pr = v * t1;                        // lane0: i*g
        float ur = __shfl_xor_sync(mask, pr, 1);  // lane1 <- i*g

        if (g == 1) {                             // owns c: v = f, t1 = o
            c = fmaf(v, c, ur);                   // c = f*c + i*g
            float h = t1 * tanh_(c);              // h = o*tanh(c)
            h_sh[pn][u] = h;
            if (YDST >= 0) yp[((size_t)t * BATCH + b) * HID + u] = h;
            if (t == T_STEPS - 1) hid[b * HID + u] = h;
        } else if (ldr) {
            x_sh[pn][u] = xr;                     // publish x(t+1)
            xr = xr2;
        }
        __syncthreads();   // ONE barrier: h_t, x_{t+1} visible; pc reads done
    }
}

// ---------------------------------------------------------------------------
// MLP head: out = GELU(hid@W1^T + b1) @ W2^T + b2, one block per row.
// ---------------------------------------------------------------------------
__global__ __launch_bounds__(H1DIM)
void head_kernel(const float* __restrict__ hid,
                 const float* __restrict__ W1, const float* __restrict__ b1,
                 const float* __restrict__ W2, const float* __restrict__ b2,
                 float* __restrict__ out)
{
    const int rr = blockIdx.x;
    const int u  = threadIdx.x;
    __shared__ float hrow[HID];
    __shared__ float h1[H1DIM];

    if (u < HID) hrow[u] = hid[rr * HID + u];
    __syncthreads();

    float s = b1[u];
#pragma unroll
    for (int m = 0; m < HID; m++) s += W1[u * HID + m] * hrow[m];
    h1[u] = 0.5f * s * (1.f + erff(s * 0.70710678118654752f));  // exact GELU
    __syncthreads();

    if (u < ODIM) {
        float s2 = b2[u];
#pragma unroll
        for (int m = 0; m < H1DIM; m++) s2 += W2[u * H1DIM + m] * h1[m];
        out[rr * ODIM + u] = s2;
    }
}

extern "C" void kernel_launch(void* const* d_in, const int* in_sizes, int n_in,
                              void* d_out, int out_size)
{
    const float* x    = (const float*)d_in[0];
    const float* Wih0 = (const float*)d_in[1];
    const float* Whh0 = (const float*)d_in[2];
    const float* bih0 = (const float*)d_in[3];
    const float* bhh0 = (const float*)d_in[4];
    const float* Wih1 = (const float*)d_in[5];
    const float* Whh1 = (const float*)d_in[6];
    const float* bih1 = (const float*)d_in[7];
    const float* bhh1 = (const float*)d_in[8];
    const float* Wih2 = (const float*)d_in[9];
    const float* Whh2 = (const float*)d_in[10];
    const float* bih2 = (const float*)d_in[11];
    const float* bhh2 = (const float*)d_in[12];
    const float* W1   = (const float*)d_in[13];
    const float* b1   = (const float*)d_in[14];
    const float* W2   = (const float*)d_in[15];
    const float* b2   = (const float*)d_in[16];

    float* out = (float*)d_out;                      // [3, 512, 18]
    float* hid = out + 3 * BATCH * ODIM;             // [3, 512, 33]

    lstm_layer_kernel<11, true,  -1, 0><<<BATCH, G4>>>(
        x, Wih0, Whh0, bih0, bhh0, hid);
    lstm_layer_kernel<33, false,  0, 1><<<BATCH, G4>>>(
        nullptr, Wih1, Whh1, bih1, bhh1, hid + BATCH * HID);
    lstm_layer_kernel<33, false,  1, -1><<<BATCH, G4>>>(
        nullptr, Wih2, Whh2, bih2, bhh2, hid + 2 * BATCH * HID);
    head_kernel<<<3 * BATCH, H1DIM>>>(hid, W1, b1, W2, b2, out);
}

// round 14
// speedup vs baseline: 1.9797x; 1.0671x over previous
#include <cuda_runtime.h>
#include <cstdint>
#include <cstddef>

#define T_STEPS 2048
#define BATCH   512
#define HID     33
#define G4      132
#define ODIM    18
#define H1DIM   72
#define NE      2      // batch elements per CTA (per thread)

// Per-layer outputs y[t][b][k] (t-major). Static device scratch (no allocs).
__device__ float g_y0[(size_t)T_STEPS * BATCH * HID];
__device__ float g_y1[(size_t)T_STEPS * BATCH * HID];

typedef unsigned long long u64;

__device__ __forceinline__ void fma2(u64 &acc, u64 a, u64 b) {
    asm("fma.rn.f32x2 %0, %1, %2, %0;" : "+l"(acc) : "l"(a), "l"(b));
}
__device__ __forceinline__ u64 pack2(float lo, float hi) {
    u64 r; asm("mov.b64 %0, {%1,%2};" : "=l"(r) : "f"(lo), "f"(hi)); return r;
}
__device__ __forceinline__ float2 unpack2(u64 v) {
    float2 r; asm("mov.b64 {%0,%1}, %2;" : "=f"(r.x), "=f"(r.y) : "l"(v)); return r;
}
__device__ __forceinline__ float sigm_(float x) {
    return __fdividef(1.f, 1.f + __expf(-x));
}
__device__ __forceinline__ float tanh_(float x) {
    float e = __expf(2.f * x);
    return 1.f - __fdividef(2.f, e + 1.f);
}

// ---------------------------------------------------------------------------
// One CTA = NE(=2) batch elements. Thread j owns fused gate row j (exactly
// R5's weights) and computes that row's dot for BOTH elements per step:
// 4 independent f32x2 chains (h0,x0,h1,x1) -> 4-way ILP. Two barriers per
// step amortized over 2 elements; phase 2 uses 66 threads (one cell update
// per (e,u)), x loaders are threads 66.. (disjoint from cell updaters).
// Per-element arithmetic identical to R5 (same op order -> same numerics).
//
// IN:   input width (11 for layer 0, 33 otherwise)
// XBF:  x layout [B,T,IN] (layer 0) vs [T,B,HID] (y buffers)
// XSRC: -1 = xin param, 0 = g_y0, 1 = g_y1
// YDST: -1 = no per-step output, 0 = g_y0, 1 = g_y1
// ---------------------------------------------------------------------------
template<int IN, bool XBF, int XSRC, int YDST>
__global__ __launch_bounds__(G4)
void lstm_layer_kernel(const float* __restrict__ xin,
                       const float* __restrict__ Wih,
                       const float* __restrict__ Whh,
                       const float* __restrict__ bih,
                       const float* __restrict__ bhh,
                       float* __restrict__ hid)
{
    constexpr int INP = ((IN + 3) / 4) * 4;   // 12 / 36
    constexpr int NPI = INP / 2;
    const int b0 = blockIdx.x * NE;
    const int j  = threadIdx.x;

    const float* xp = (XSRC == 0) ? g_y0 : (XSRC == 1) ? g_y1 : xin;
    float* yp = (YDST == 0) ? g_y0 : (YDST == 1) ? g_y1 : nullptr;

    __shared__ __align__(16) float h_sh[NE][36];   // single-buffered (phase-split safe)
    __shared__ __align__(16) float x_sh[NE][36];
    __shared__ float g_sh[NE][G4];

    // ---- pack weights (identical to R5) ----
    u64 whh2[18];
#pragma unroll
    for (int p = 0; p < 18; p++) {
        int m = 2 * p;
        float lo = (m     < HID) ? Whh[j * HID + m]     : 0.f;
        float hi = (m + 1 < HID) ? Whh[j * HID + m + 1] : 0.f;
        whh2[p] = pack2(lo, hi);
    }
    u64 wih2[NPI];
#pragma unroll
    for (int p = 0; p < NPI; p++) {
        int m = 2 * p;
        float lo = (m     < IN) ? Wih[j * IN + m]     : 0.f;
        float hi = (m + 1 < IN) ? Wih[j * IN + m + 1] : 0.f;
        wih2[p] = pack2(lo, hi);
    }
    const float bias = bih[j] + bhh[j];
    const bool is_g  = (j >= 66 && j < 99);   // gate order i,f,g,o

    // cell-update role: threads 0..65 -> (e, u)
    const int ce = j / 33;            // valid for j < 66
    const int cu = j % 33;

    // x-loader role: threads 66..66+IN-1 -> e0, 99..99+IN-1 -> e1
    int le = -1, li = 0;
    if (j >= 66 && j < 66 + IN)      { le = 0; li = j - 66; }
    else if (j >= 99 && j < 99 + IN) { le = 1; li = j - 99; }

    auto xval = [&](int e, int t, int i) -> float {
        if (XBF) return xp[((size_t)(b0 + e) * T_STEPS + t) * IN + i];
        else     return xp[((size_t)t * BATCH + (b0 + e)) * HID + i];
    };

    // ---- init shared state (zeros incl. pads) ----
    for (int i = j; i < NE * 36; i += G4) {
        (&h_sh[0][0])[i] = 0.f;
        (&x_sh[0][0])[i] = 0.f;
    }
    __syncthreads();
    if (le >= 0) x_sh[le][li] = xval(le, 0, li);
    __syncthreads();

    float c  = 0.f;                                   // cell (threads j<66)
    float xr = (le >= 0) ? xval(le, 1, li) : 0.f;     // x(t+1) entering step t

    for (int t = 0; t < T_STEPS; ++t) {
        // depth-2 x prefetch (long-scoreboard hidden across steps)
        float xr2 = 0.f;
        if (le >= 0 && (t + 2) < T_STEPS) xr2 = xval(le, t + 2, li);

        // 4 independent f32x2 chains: (h,x) x (e0,e1)
        u64 ah0 = 0ull, ax0 = 0ull, ah1 = 0ull, ax1 = 0ull;
        const ulonglong2* hv0 = (const ulonglong2*)h_sh[0];
        const ulonglong2* hv1 = (const ulonglong2*)h_sh[1];
        const ulonglong2* xv0 = (const ulonglong2*)x_sh[0];
        const ulonglong2* xv1 = (const ulonglong2*)x_sh[1];
#pragma unroll
        for (int q = 0; q < 9; q++) {
            ulonglong2 v0 = hv0[q];                  // LDS.128 broadcast
            ulonglong2 v1 = hv1[q];
            fma2(ah0, whh2[2 * q],     v0.x);
            fma2(ah1, whh2[2 * q],     v1.x);
            fma2(ah0, whh2[2 * q + 1], v0.y);
            fma2(ah1, whh2[2 * q + 1], v1.y);
        }
#pragma unroll
        for (int q = 0; q < INP / 4; q++) {
            ulonglong2 v0 = xv0[q];
            ulonglong2 v1 = xv1[q];
            fma2(ax0, wih2[2 * q],     v0.x);
            fma2(ax1, wih2[2 * q],     v1.x);
            fma2(ax0, wih2[2 * q + 1], v0.y);
            fma2(ax1, wih2[2 * q + 1], v1.y);
        }
        {
            float2 ah = unpack2(ah0), ax = unpack2(ax0);
            float pre = (ah.x + ah.y) + (ax.x + ax.y) + bias;
            g_sh[0][j] = is_g ? tanh_(pre) : sigm_(pre);
        }
        {
            float2 ah = unpack2(ah1), ax = unpack2(ax1);
            float pre = (ah.x + ah.y) + (ax.x + ax.y) + bias;
            g_sh[1][j] = is_g ? tanh_(pre) : sigm_(pre);
        }
        __syncthreads();   // B1: gates visible; all h/x reads of step t done

        if (j < 66) {
            float gi = g_sh[ce][cu];
            float gf = g_sh[ce][cu + 33];
            float gg = g_sh[ce][cu + 66];
            float go = g_sh[ce][cu + 99];
            c = gf * c + gi * gg;
            float h = go * tanh_(c);
            h_sh[ce][cu] = h;
            if (YDST >= 0) yp[((size_t)t * BATCH + (b0 + ce)) * HID + cu] = h;
            if (t == T_STEPS - 1) hid[(b0 + ce) * HID + cu] = h;
        } else if (le >= 0) {
            x_sh[le][li] = xr;    // publish x(t+1)
            xr = xr2;
        }
        __syncthreads();   // B2: h_t, x_{t+1} visible for step t+1 reads
    }
}

// ---------------------------------------------------------------------------
// MLP head: out = GELU(hid@W1^T + b1) @ W2^T + b2, one block per row.
// ---------------------------------------------------------------------------
__global__ __launch_bounds__(H1DIM)
void head_kernel(const float* __restrict__ hid,
                 const float* __restrict__ W1, const float* __restrict__ b1,
                 const float* __restrict__ W2, const float* __restrict__ b2,
                 float* __restrict__ out)
{
    const int rr = blockIdx.x;
    const int u  = threadIdx.x;
    __shared__ float hrow[HID];
    __shared__ float h1[H1DIM];

    if (u < HID) hrow[u] = hid[rr * HID + u];
    __syncthreads();

    float s = b1[u];
#pragma unroll
    for (int m = 0; m < HID; m++) s += W1[u * HID + m] * hrow[m];
    h1[u] = 0.5f * s * (1.f + erff(s * 0.70710678118654752f));  // exact GELU
    __syncthreads();

    if (u < ODIM) {
        float s2 = b2[u];
#pragma unroll
        for (int m = 0; m < H1DIM; m++) s2 += W2[u * H1DIM + m] * h1[m];
        out[rr * ODIM + u] = s2;
    }
}

extern "C" void kernel_launch(void* const* d_in, const int* in_sizes, int n_in,
                              void* d_out, int out_size)
{
    const float* x    = (const float*)d_in[0];
    const float* Wih0 = (const float*)d_in[1];
    const float* Whh0 = (const float*)d_in[2];
    const float* bih0 = (const float*)d_in[3];
    const float* bhh0 = (const float*)d_in[4];
    const float* Wih1 = (const float*)d_in[5];
    const float* Whh1 = (const float*)d_in[6];
    const float* bih1 = (const float*)d_in[7];
    const float* bhh1 = (const float*)d_in[8];
    const float* Wih2 = (const float*)d_in[9];
    const float* Whh2 = (const float*)d_in[10];
    const float* bih2 = (const float*)d_in[11];
    const float* bhh2 = (const float*)d_in[12];
    const float* W1   = (const float*)d_in[13];
    const float* b1   = (const float*)d_in[14];
    const float* W2   = (const float*)d_in[15];
    const float* b2   = (const float*)d_in[16];

    float* out = (float*)d_out;                      // [3, 512, 18]
    float* hid = out + 3 * BATCH * ODIM;             // [3, 512, 33]

    const int grid = BATCH / NE;   // 256

    lstm_layer_kernel<11, true,  -1, 0><<<grid, G4>>>(
        x, Wih0, Whh0, bih0, bhh0, hid);
    lstm_layer_kernel<33, false,  0, 1><<<grid, G4>>>(
        nullptr, Wih1, Whh1, bih1, bhh1, hid + BATCH * HID);
    lstm_layer_kernel<33, false,  1, -1><<<grid, G4>>>(
        nullptr, Wih2, Whh2, bih2, bhh2, hid + 2 * BATCH * HID);
    head_kernel<<<3 * BATCH, H1DIM>>>(hid, W1, b1, W2, b2, out);
}